// round 13
// baseline (speedup 1.0000x reference)
#include <cuda_runtime.h>
#include <cuda_bf16.h>
#include <cuda_fp16.h>
#include <cstdint>

// ---------------- Problem constants ----------------
#define B_     16384
#define F_     26
#define V_     100000
#define E_     16
#define CONT_  13
#define K1_    429     // CONT_ + F_*E_
#define KP_    448     // padded K for BOTH GEMMs (mult of 64)
#define H_     400
#define NT_    80      // CTA N tile (5 * 80 = 400, exact)

// A-tile (dnn_in) layout per k-block kb: fields 4kb..4kb+3 (kb<6);
// kb==6: fields 24,25 (bytes 0..63) | cont (bytes 64..89) | zeros (90..127).
// h1 layout (KP_): [ h1 0..399 | zero 400..447 ]  (pad never written; zero-init)

// ---------------- Scratch (device globals) ----------------
__device__ __align__(256) __half g_h1  [(size_t)B_ * KP_];
__device__ __align__(256) __half g_w1t [(size_t)H_ * KP_];  // [n][k] dnn layout
__device__ __align__(256) __half g_w2t [(size_t)H_ * KP_];  // [n][k] = fp16(W2[k][n])
__device__ float g_fm  [B_];
__device__ float g_part[5][B_];
__device__ int   g_cnt [B_ / 128];      // zero-init; self-resetting

// ---------------- PTX helpers ----------------
__device__ __forceinline__ uint32_t smem_u32(const void* p) {
    return (uint32_t)__cvta_generic_to_shared(p);
}
#define CP16(dst_u32, src) \
    asm volatile("cp.async.cg.shared.global [%0], [%1], 16;" :: "r"(dst_u32), "l"(src))
#define CP_COMMIT() asm volatile("cp.async.commit_group;" ::: "memory")
#define CP_WAIT0()  asm volatile("cp.async.wait_group 0;" ::: "memory")
#define CP_WAIT1()  asm volatile("cp.async.wait_group 1;" ::: "memory")

#define LDSM_X4(r0, r1, r2, r3, addr)                                          \
    asm volatile("ldmatrix.sync.aligned.m8n8.x4.shared.b16 {%0,%1,%2,%3},[%4];"\
                 : "=r"(r0), "=r"(r1), "=r"(r2), "=r"(r3) : "r"(addr))
#define LDSM_X2(r0, r1, addr)                                                  \
    asm volatile("ldmatrix.sync.aligned.m8n8.x2.shared.b16 {%0,%1},[%2];"      \
                 : "=r"(r0), "=r"(r1) : "r"(addr))
#define STS128(addr, x, y, z, w)                                               \
    asm volatile("st.shared.v4.b32 [%0], {%1,%2,%3,%4};"                       \
                 :: "r"(addr), "r"(x), "r"(y), "r"(z), "r"(w))
#define STS32(addr, x) asm volatile("st.shared.b32 [%0], %1;" :: "r"(addr), "r"(x))
#define STS16(addr, x) asm volatile("st.shared.u16 [%0], %1;" :: "r"(addr), "h"(x))

__device__ __forceinline__ void mma_fp16(float* c,
                                         uint32_t a0, uint32_t a1, uint32_t a2, uint32_t a3,
                                         uint32_t b0, uint32_t b1) {
    asm volatile(
        "mma.sync.aligned.m16n8k16.row.col.f32.f16.f16.f32 "
        "{%0,%1,%2,%3},{%4,%5,%6,%7},{%8,%9},{%0,%1,%2,%3};"
        : "+f"(c[0]), "+f"(c[1]), "+f"(c[2]), "+f"(c[3])
        : "r"(a0), "r"(a1), "r"(a2), "r"(a3), "r"(b0), "r"(b1));
}

__device__ __forceinline__ uint32_t pack2(float a, float b) {
    __half h0 = __float2half_rn(a), h1 = __float2half_rn(b);
    return (uint32_t)__half_as_ushort(h0) | ((uint32_t)__half_as_ushort(h1) << 16);
}

// ============================================================================
// Prep: weights -> fp16 K-major (dnn-permuted W1T, plain W2T), padded to 448
// ============================================================================
__global__ void prep_kernel(const float* __restrict__ W1, const float* __restrict__ W2) {
    int idx = blockIdx.x * blockDim.x + threadIdx.x;
    if (idx >= H_ * KP_) return;
    int n = idx / KP_, k = idx % KP_;

    float v1;
    if (k < 416)      v1 = W1[(size_t)(CONT_ + k) * H_ + n];   // emb part
    else if (k < 429) v1 = W1[(size_t)(k - 416) * H_ + n];     // cont part
    else              v1 = 0.f;
    g_w1t[idx] = __float2half_rn(v1);

    float v2 = (k < H_) ? W2[(size_t)k * H_ + n] : 0.f;
    g_w2t[idx] = __float2half_rn(v2);
}

// ============================================================================
// GEMM1 fused: gather(emb->fp16, in-SMEM) + FM (x==0 CTAs) + GEMM + relu+bias.
//   CTA 128(M) x 80(N), 4 warps, warp tile 64x40, BK=64, K=448 (7 blocks).
//   Thread r owns sample row m0+r for the gather & FM (no shuffles).
// ============================================================================
#define ROWB_  144
#define OFFB_  (128 * ROWB_)
#define STAGE_ ((128 + NT_) * ROWB_)     // 29952

__global__ void __launch_bounds__(128)
gemm1_fused(const float* __restrict__ cont, const int* __restrict__ cat,
            const float* __restrict__ w_cont, const float* __restrict__ b_cont,
            const float* __restrict__ t_first, const float* __restrict__ t_emb,
            const __half* __restrict__ W1t, const float* __restrict__ bias,
            __half* __restrict__ C) {
    extern __shared__ char smem_raw[];
    __shared__ int cat_s[128 * F_];
    const uint32_t sbase = smem_u32(smem_raw);

    const int tid  = threadIdx.x;
    const int warp = tid >> 5, lane = tid & 31;
    const int gr = lane >> 2, gc = lane & 3;
    const int wm  = (warp >> 1) * 64;
    const int wni = warp & 1;
    const int wn  = wni * 40;
    const int m0 = blockIdx.y * 128;
    const int n0 = blockIdx.x * NT_;

    const int lane8 = lane & 7;
    const int laneH = (lane >> 3) & 1;
    const int laneK = lane >> 4;
    const uint32_t aoff  = (uint32_t)((wm + lane8 + laneH * 8) * ROWB_ + laneK * 16);
    const uint32_t boff4 = (uint32_t)((wn + lane8 + laneK * 8) * ROWB_ + laneH * 16);
    const uint32_t boff2 = (uint32_t)((wn + 32 + lane8) * ROWB_ + laneH * 16);

    // cat rows for this M tile (contiguous)
    #pragma unroll
    for (int h = 0; h < F_; h++) {
        int i = tid + h * 128;
        cat_s[i] = cat[m0 * F_ + i];
    }
    __syncthreads();

    const bool do_fm = (blockIdx.x == 0);
    float S[16];
    #pragma unroll
    for (int e = 0; e < 16; e++) S[e] = 0.f;
    float q = 0.f, scal = 0.f;

    float acc[4][5][4];
    #pragma unroll
    for (int i = 0; i < 4; i++)
        #pragma unroll
        for (int j = 0; j < 5; j++)
            #pragma unroll
            for (int k = 0; k < 4; k++) acc[i][j][k] = 0.f;

    // ---- gather one A k-block into stage buffer (thread = row) ----
    auto gather_A = [&](int kb, int buf) {
        const uint32_t rowbase = sbase + buf * STAGE_ + tid * ROWB_;
        const int nf = (kb < 6) ? 4 : 2;
        for (int j = 0; j < nf; j++) {
            int f = kb * 4 + j;
            int idx = cat_s[tid * F_ + f];
            const float4* src =
                reinterpret_cast<const float4*>(t_emb + ((size_t)f * V_ + (size_t)idx) * E_);
            float4 r0 = src[0], r1 = src[1], r2 = src[2], r3 = src[3];
            uint32_t p0 = pack2(r0.x, r0.y), p1 = pack2(r0.z, r0.w);
            uint32_t p2 = pack2(r1.x, r1.y), p3 = pack2(r1.z, r1.w);
            uint32_t p4 = pack2(r2.x, r2.y), p5 = pack2(r2.z, r2.w);
            uint32_t p6 = pack2(r3.x, r3.y), p7 = pack2(r3.z, r3.w);
            STS128(rowbase + j * 32,      p0, p1, p2, p3);
            STS128(rowbase + j * 32 + 16, p4, p5, p6, p7);
            if (do_fm) {
                S[0]+=r0.x; S[1]+=r0.y; S[2]+=r0.z; S[3]+=r0.w;
                S[4]+=r1.x; S[5]+=r1.y; S[6]+=r1.z; S[7]+=r1.w;
                S[8]+=r2.x; S[9]+=r2.y; S[10]+=r2.z; S[11]+=r2.w;
                S[12]+=r3.x; S[13]+=r3.y; S[14]+=r3.z; S[15]+=r3.w;
                q = fmaf(r0.x,r0.x,q); q = fmaf(r0.y,r0.y,q);
                q = fmaf(r0.z,r0.z,q); q = fmaf(r0.w,r0.w,q);
                q = fmaf(r1.x,r1.x,q); q = fmaf(r1.y,r1.y,q);
                q = fmaf(r1.z,r1.z,q); q = fmaf(r1.w,r1.w,q);
                q = fmaf(r2.x,r2.x,q); q = fmaf(r2.y,r2.y,q);
                q = fmaf(r2.z,r2.z,q); q = fmaf(r2.w,r2.w,q);
                q = fmaf(r3.x,r3.x,q); q = fmaf(r3.y,r3.y,q);
                q = fmaf(r3.z,r3.z,q); q = fmaf(r3.w,r3.w,q);
                scal += t_first[(size_t)f * V_ + (size_t)idx];
            }
        }
        if (kb == 6) {   // cont cols 416..428 at bytes 64..89; zeros 90..127
            const float* crow = cont + (size_t)(m0 + tid) * CONT_;
            #pragma unroll
            for (int i = 0; i < 6; i++) {
                float c0 = crow[2 * i], c1 = crow[2 * i + 1];
                if (do_fm) {
                    scal = fmaf(c0, w_cont[2 * i],     scal);
                    scal = fmaf(c1, w_cont[2 * i + 1], scal);
                }
                STS32(rowbase + 64 + 4 * i, pack2(c0, c1));
            }
            float c12 = crow[12];
            if (do_fm) scal = fmaf(c12, w_cont[12], scal);
            STS16(rowbase + 88, __half_as_ushort(__float2half_rn(c12)));
            STS16(rowbase + 90, (unsigned short)0);
            #pragma unroll
            for (int i = 0; i < 9; i++) STS32(rowbase + 92 + 4 * i, 0u);
        }
    };

    // ---- B tile loader (80 rows x 8 chunks = 640 = 5 per thread) ----
    auto load_B = [&](int kb, int buf) {
        const uint32_t st = sbase + buf * STAGE_ + OFFB_;
        #pragma unroll
        for (int h = 0; h < 5; h++) {
            int c = tid + h * 128;
            int row = c >> 3, q8 = c & 7;
            CP16(st + row * ROWB_ + q8 * 16,
                 W1t + (size_t)(n0 + row) * KP_ + kb * 64 + q8 * 8);
        }
    };

    gather_A(0, 0);
    load_B(0, 0); CP_COMMIT();

    for (int kb = 0; kb < 7; kb++) {
        const int buf = kb & 1;
        if (kb + 1 < 7) {
            load_B(kb + 1, buf ^ 1); CP_COMMIT();
            gather_A(kb + 1, buf ^ 1);
            CP_WAIT1();
        } else {
            CP_WAIT0();
        }
        __syncthreads();

        const uint32_t st = sbase + buf * STAGE_;
        #pragma unroll
        for (int ks = 0; ks < 4; ks++) {
            const uint32_t ko = ks * 32;
            uint32_t ah[4][4], bh[5][2];
            #pragma unroll
            for (int mi = 0; mi < 4; mi++) {
                uint32_t ad = st + aoff + mi * (16 * ROWB_) + ko;
                LDSM_X4(ah[mi][0], ah[mi][1], ah[mi][2], ah[mi][3], ad);
            }
            #pragma unroll
            for (int nj = 0; nj < 2; nj++) {
                uint32_t bd = st + OFFB_ + boff4 + nj * (16 * ROWB_) + ko;
                LDSM_X4(bh[nj*2][0], bh[nj*2][1], bh[nj*2+1][0], bh[nj*2+1][1], bd);
            }
            LDSM_X2(bh[4][0], bh[4][1], st + OFFB_ + boff2 + ko);

            #pragma unroll
            for (int mi = 0; mi < 4; mi++)
                #pragma unroll
                for (int ni = 0; ni < 5; ni++)
                    mma_fp16(acc[mi][ni], ah[mi][0], ah[mi][1], ah[mi][2], ah[mi][3],
                             bh[ni][0], bh[ni][1]);
        }
        __syncthreads();
    }

    if (do_fm) {
        float ss = 0.f;
        #pragma unroll
        for (int e = 0; e < 16; e++) ss = fmaf(S[e], S[e], ss);
        g_fm[m0 + tid] = scal + b_cont[0] + 0.5f * (ss - q);
    }

    // ---- epilogue: relu(+bias) -> h1 fp16 (ldc = KP_) ----
    #pragma unroll
    for (int mi = 0; mi < 4; mi++) {
        int r = m0 + wm + mi * 16 + gr;
        #pragma unroll
        for (int ni = 0; ni < 5; ni++) {
            int n = n0 + wn + ni * 8 + gc * 2;
            float b0v = bias[n], b1v = bias[n + 1];
            #pragma unroll
            for (int half = 0; half < 2; half++) {
                float x0 = fmaxf(acc[mi][ni][half * 2 + 0] + b0v, 0.f);
                float x1 = fmaxf(acc[mi][ni][half * 2 + 1] + b1v, 0.f);
                size_t o = (size_t)(r + half * 8) * KP_ + n;
                *reinterpret_cast<uint32_t*>(C + o) = pack2(x0, x1);
            }
        }
    }
}

// ============================================================================
// GEMM2 (fused finish): same geometry, BK=64, K=448, A = h1 from GMEM.
// ============================================================================
__global__ void __launch_bounds__(128)
gemm2_fused(const __half* __restrict__ A,
            const __half* __restrict__ Bh,
            const float* __restrict__ bias,
            const float* __restrict__ Wout,
            const float* __restrict__ bout,
            float* __restrict__ out) {
    constexpr int CPR = 8;
    constexpr int NCH = (128 + NT_) * CPR;   // 1664
    constexpr int NIT = NCH / 128;           // 13

    extern __shared__ char smem_raw[];
    __shared__ float part[2][128];
    __shared__ int   s_done;
    const uint32_t sbase = smem_u32(smem_raw);

    const int tid  = threadIdx.x;
    const int warp = tid >> 5, lane = tid & 31;
    const int gr = lane >> 2, gc = lane & 3;
    const int wm  = (warp >> 1) * 64;
    const int wni = warp & 1;
    const int wn  = wni * 40;
    const int m0 = blockIdx.y * 128;
    const int n0 = blockIdx.x * NT_;

    const int lane8 = lane & 7;
    const int laneH = (lane >> 3) & 1;
    const int laneK = lane >> 4;
    const uint32_t aoff  = (uint32_t)((wm + lane8 + laneH * 8) * ROWB_ + laneK * 16);
    const uint32_t boff4 = (uint32_t)((wn + lane8 + laneK * 8) * ROWB_ + laneH * 16);
    const uint32_t boff2 = (uint32_t)((wn + 32 + lane8) * ROWB_ + laneH * 16);

    float acc[4][5][4];
    #pragma unroll
    for (int i = 0; i < 4; i++)
        #pragma unroll
        for (int j = 0; j < 5; j++)
            #pragma unroll
            for (int k = 0; k < 4; k++) acc[i][j][k] = 0.f;

    #define LOAD_KB2(KB, BUF)                                                       \
    do {                                                                            \
        const int k0_ = (KB) * 64;                                                  \
        const uint32_t st_ = sbase + (BUF) * STAGE_;                                \
        _Pragma("unroll")                                                           \
        for (int h = 0; h < NIT; h++) {                                             \
            int c_ = tid + h * 128;                                                 \
            int row_ = c_ / CPR, q_ = c_ % CPR;                                     \
            if (row_ < 128) {                                                       \
                CP16(st_ + row_ * ROWB_ + q_ * 16,                                  \
                     A + (size_t)(m0 + row_) * KP_ + k0_ + q_ * 8);                 \
            } else {                                                                \
                int r2_ = row_ - 128;                                               \
                CP16(st_ + OFFB_ + r2_ * ROWB_ + q_ * 16,                           \
                     Bh + (size_t)(n0 + r2_) * KP_ + k0_ + q_ * 8);                 \
            }                                                                       \
        }                                                                           \
    } while (0)

    LOAD_KB2(0, 0);
    CP_COMMIT();

    for (int kb = 0; kb < 7; kb++) {
        const int buf = kb & 1;
        if (kb + 1 < 7) { LOAD_KB2(kb + 1, buf ^ 1); CP_COMMIT(); CP_WAIT1(); }
        else            { CP_WAIT0(); }
        __syncthreads();

        const uint32_t st = sbase + buf * STAGE_;
        #pragma unroll
        for (int ks = 0; ks < 4; ks++) {
            const uint32_t ko = ks * 32;
            uint32_t ah[4][4], bh[5][2];
            #pragma unroll
            for (int mi = 0; mi < 4; mi++) {
                uint32_t ad = st + aoff + mi * (16 * ROWB_) + ko;
                LDSM_X4(ah[mi][0], ah[mi][1], ah[mi][2], ah[mi][3], ad);
            }
            #pragma unroll
            for (int nj = 0; nj < 2; nj++) {
                uint32_t bd = st + OFFB_ + boff4 + nj * (16 * ROWB_) + ko;
                LDSM_X4(bh[nj*2][0], bh[nj*2][1], bh[nj*2+1][0], bh[nj*2+1][1], bd);
            }
            LDSM_X2(bh[4][0], bh[4][1], st + OFFB_ + boff2 + ko);

            #pragma unroll
            for (int mi = 0; mi < 4; mi++)
                #pragma unroll
                for (int ni = 0; ni < 5; ni++)
                    mma_fp16(acc[mi][ni], ah[mi][0], ah[mi][1], ah[mi][2], ah[mi][3],
                             bh[ni][0], bh[ni][1]);
        }
        __syncthreads();
    }
    #undef LOAD_KB2

    // ---- epilogue: dot with Wout; last CTA per M-tile writes out ----
    #pragma unroll
    for (int mi = 0; mi < 4; mi++) {
        float s0 = 0.f, s1 = 0.f;
        #pragma unroll
        for (int ni = 0; ni < 5; ni++) {
            int n = n0 + wn + ni * 8 + gc * 2;
            float w0v = Wout[1 + n], w1v = Wout[2 + n];
            float b0v = bias[n],     b1v = bias[n + 1];
            s0 = fmaf(fmaxf(acc[mi][ni][0] + b0v, 0.f), w0v, s0);
            s0 = fmaf(fmaxf(acc[mi][ni][1] + b1v, 0.f), w1v, s0);
            s1 = fmaf(fmaxf(acc[mi][ni][2] + b0v, 0.f), w0v, s1);
            s1 = fmaf(fmaxf(acc[mi][ni][3] + b1v, 0.f), w1v, s1);
        }
        s0 += __shfl_xor_sync(0xffffffffu, s0, 1);
        s0 += __shfl_xor_sync(0xffffffffu, s0, 2);
        s1 += __shfl_xor_sync(0xffffffffu, s1, 1);
        s1 += __shfl_xor_sync(0xffffffffu, s1, 2);
        if (gc == 0) {
            part[wni][wm + mi * 16 + gr]     = s0;
            part[wni][wm + mi * 16 + gr + 8] = s1;
        }
    }
    __syncthreads();
    g_part[blockIdx.x][m0 + tid] = part[0][tid] + part[1][tid];
    __threadfence();
    __syncthreads();
    if (tid == 0) s_done = atomicAdd(&g_cnt[blockIdx.y], 1);
    __syncthreads();
    if (s_done == 4) {
        __threadfence();
        int b = m0 + tid;
        float s = g_part[0][b] + g_part[1][b] + g_part[2][b] +
                  g_part[3][b] + g_part[4][b];
        out[b] = fmaf(g_fm[b], Wout[0], bout[0] + s);
        if (tid == 0) g_cnt[blockIdx.y] = 0;   // reset for next replay
    }
}

// ============================================================================
// Launch
// ============================================================================
static void* sym_addr(const void* symbol) {
    void* p = nullptr;
    cudaGetSymbolAddress(&p, symbol);
    return p;
}

extern "C" void kernel_launch(void* const* d_in, const int* in_sizes, int n_in,
                              void* d_out, int out_size) {
    const float* cont    = (const float*)d_in[0];
    const int*   cat     = (const int*)  d_in[1];
    const float* w_cont  = (const float*)d_in[2];
    const float* b_cont  = (const float*)d_in[3];
    const float* t_first = (const float*)d_in[4];
    const float* t_emb   = (const float*)d_in[5];
    const float* W1      = (const float*)d_in[6];
    const float* b1      = (const float*)d_in[7];
    const float* W2      = (const float*)d_in[8];
    const float* b2      = (const float*)d_in[9];
    const float* Wout    = (const float*)d_in[10];
    const float* bout    = (const float*)d_in[11];
    float* out = (float*)d_out;

    const int SMEM = 2 * STAGE_;   // 59904
    cudaFuncSetAttribute(gemm1_fused, cudaFuncAttributeMaxDynamicSharedMemorySize, SMEM);
    cudaFuncSetAttribute(gemm2_fused, cudaFuncAttributeMaxDynamicSharedMemorySize, SMEM);

    __half* h1  = (__half*)sym_addr(g_h1);
    __half* w1t = (__half*)sym_addr(g_w1t);
    __half* w2t = (__half*)sym_addr(g_w2t);

    // 1) weight prep (400*448 = 179200 elems)
    prep_kernel<<<(H_ * KP_ + 255) / 256, 256>>>(W1, W2);

    // 2) fused gather+FM+GEMM1: h1 = relu(dnn_in @ W1 + b1)
    dim3 grid(5, B_ / 128);
    gemm1_fused<<<grid, 128, SMEM>>>(cont, cat, w_cont, b_cont, t_first, t_emb,
                                     w1t, b1, h1);

    // 3) fused GEMM2 + finish: out = fm*Wout[0] + b_out + relu(h1@W2+b2).Wout[1:]
    gemm2_fused<<<grid, 128, SMEM>>>(h1, w2t, b2, Wout, bout, out);
}

// round 14
// speedup vs baseline: 1.5646x; 1.5646x over previous
#include <cuda_runtime.h>
#include <cuda_bf16.h>
#include <cuda_fp16.h>
#include <cstdint>

// ---------------- Problem constants ----------------
#define B_     16384
#define F_     26
#define V_     100000
#define E_     16
#define CONT_  13
#define K1_    429     // CONT_ + F_*E_
#define KP_    448     // padded K for BOTH GEMMs (mult of 64)
#define H_     400
#define NT_    80      // CTA N tile (5 * 80 = 400, exact)

// dnn_in layout (KP_): [ emb 0..415 | cont 416..428 | zero 429..447 ]
// h1 layout (KP_):     [ h1 0..399 | zero 400..447 ]  (pad never written; zero-init)

// ---------------- Scratch (device globals) ----------------
__device__ __align__(256) __half g_dnn [(size_t)B_ * KP_];
__device__ __align__(256) __half g_h1  [(size_t)B_ * KP_];
__device__ __align__(256) __half g_w1t [(size_t)H_ * KP_];
__device__ __align__(256) __half g_w2t [(size_t)H_ * KP_];
__device__ float g_fm  [B_];
__device__ float g_part[5][B_];
__device__ int   g_cnt [B_ / 128];      // zero-init; self-resetting

// ---------------- PTX helpers ----------------
__device__ __forceinline__ uint32_t smem_u32(const void* p) {
    return (uint32_t)__cvta_generic_to_shared(p);
}
#define CP16(dst_u32, src) \
    asm volatile("cp.async.cg.shared.global [%0], [%1], 16;" :: "r"(dst_u32), "l"(src))
#define CP_COMMIT() asm volatile("cp.async.commit_group;" ::: "memory")
#define CP_WAIT0()  asm volatile("cp.async.wait_group 0;" ::: "memory")
#define CP_WAIT1()  asm volatile("cp.async.wait_group 1;" ::: "memory")

#define LDSM_X4(r0, r1, r2, r3, addr)                                          \
    asm volatile("ldmatrix.sync.aligned.m8n8.x4.shared.b16 {%0,%1,%2,%3},[%4];"\
                 : "=r"(r0), "=r"(r1), "=r"(r2), "=r"(r3) : "r"(addr))
#define LDSM_X2(r0, r1, addr)                                                  \
    asm volatile("ldmatrix.sync.aligned.m8n8.x2.shared.b16 {%0,%1},[%2];"      \
                 : "=r"(r0), "=r"(r1) : "r"(addr))

__device__ __forceinline__ void mma_fp16(float* c,
                                         uint32_t a0, uint32_t a1, uint32_t a2, uint32_t a3,
                                         uint32_t b0, uint32_t b1) {
    asm volatile(
        "mma.sync.aligned.m16n8k16.row.col.f32.f16.f16.f32 "
        "{%0,%1,%2,%3},{%4,%5,%6,%7},{%8,%9},{%0,%1,%2,%3};"
        : "+f"(c[0]), "+f"(c[1]), "+f"(c[2]), "+f"(c[3])
        : "r"(a0), "r"(a1), "r"(a2), "r"(a3), "r"(b0), "r"(b1));
}

// ============================================================================
// Kernel 1 (merged): blocks [0, 2048): gather + FM (one warp per sample);
//                    blocks [2048, 2748): weight prep.
// ============================================================================
#define GATHER_BLKS (B_ / 8)     // 2048
#define PREP_BLKS   700          // ceil(400*448 / 256)

__global__ void gather_prep_kernel(const float* __restrict__ cont,
                                   const int*   __restrict__ cat,
                                   const float* __restrict__ w_cont,
                                   const float* __restrict__ b_cont,
                                   const float* __restrict__ t_first,
                                   const float* __restrict__ t_emb,
                                   const float* __restrict__ W1,
                                   const float* __restrict__ W2) {
    if (blockIdx.x >= GATHER_BLKS) {
        int idx = (blockIdx.x - GATHER_BLKS) * 256 + threadIdx.x;
        if (idx < H_ * KP_) {
            int n = idx / KP_, k = idx % KP_;
            float v1;
            if (k < 416)      v1 = W1[(size_t)(CONT_ + k) * H_ + n];   // emb part
            else if (k < 429) v1 = W1[(size_t)(k - 416) * H_ + n];     // cont part
            else              v1 = 0.f;
            g_w1t[idx] = __float2half_rn(v1);

            float v2 = (k < H_) ? W2[(size_t)k * H_ + n] : 0.f;
            g_w2t[idx] = __float2half_rn(v2);
        }
        return;
    }

    int warp = (blockIdx.x * blockDim.x + threadIdx.x) >> 5;
    int lane = threadIdx.x & 31;
    const int b = warp;

    float v[16];
    #pragma unroll
    for (int i = 0; i < 16; i++) v[i] = 0.f;
    float q = 0.f, scal = 0.f;

    if (lane < F_) {
        int idx = cat[b * F_ + lane];
        const float4* row =
            reinterpret_cast<const float4*>(t_emb + ((size_t)lane * V_ + (size_t)idx) * E_);
        float4 r0 = row[0], r1 = row[1], r2 = row[2], r3 = row[3];
        v[0]=r0.x; v[1]=r0.y; v[2]=r0.z; v[3]=r0.w;
        v[4]=r1.x; v[5]=r1.y; v[6]=r1.z; v[7]=r1.w;
        v[8]=r2.x; v[9]=r2.y; v[10]=r2.z; v[11]=r2.w;
        v[12]=r3.x; v[13]=r3.y; v[14]=r3.z; v[15]=r3.w;

        uint32_t pk[8];
        #pragma unroll
        for (int i = 0; i < 8; i++) {
            __half h0 = __float2half_rn(v[2*i]);
            __half h1 = __float2half_rn(v[2*i+1]);
            pk[i] = (uint32_t)__half_as_ushort(h0) | ((uint32_t)__half_as_ushort(h1) << 16);
            q = fmaf(v[2*i],   v[2*i],   q);
            q = fmaf(v[2*i+1], v[2*i+1], q);
        }
        uint4* dst = reinterpret_cast<uint4*>(g_dnn + (size_t)b * KP_ + lane * E_);
        dst[0] = make_uint4(pk[0], pk[1], pk[2], pk[3]);
        dst[1] = make_uint4(pk[4], pk[5], pk[6], pk[7]);
        scal = t_first[(size_t)lane * V_ + (size_t)idx];
    }
    if (lane < CONT_) {
        float c = cont[b * CONT_ + lane];
        g_dnn[(size_t)b * KP_ + 416 + lane] = __float2half_rn(c);
        scal = fmaf(c, w_cont[lane], scal);
    }
    if (lane < KP_ - K1_) {     // zero cols 429..447 (19 lanes)
        g_dnn[(size_t)b * KP_ + K1_ + lane] = __ushort_as_half((unsigned short)0);
    }

    #pragma unroll
    for (int off = 16; off; off >>= 1) {
        #pragma unroll
        for (int e = 0; e < 16; e++)
            v[e] += __shfl_xor_sync(0xffffffffu, v[e], off);
        q    += __shfl_xor_sync(0xffffffffu, q,    off);
        scal += __shfl_xor_sync(0xffffffffu, scal, off);
    }
    if (lane == 0) {
        float ss = 0.f;
        #pragma unroll
        for (int e = 0; e < 16; e++) ss = fmaf(v[e], v[e], ss);
        g_fm[b] = scal + b_cont[0] + 0.5f * (ss - q);
    }
}

// ============================================================================
// fp16 GEMM via mma.sync m16n8k16. CTA 128(M) x 80(N), 4 warps (2M x 2N),
//   warp tile 64x40, 128 threads, BK=64, K=448 (7 k-blocks), double-buffered.
//   (R12-measured best geometry for BOTH GEMMs: 0.246 HMMA/cyc/SM.)
//   FUSE=0: relu(+bias) -> C fp16 (ldc=KP_).
//   FUSE=1: fused dot w/ Wout -> g_part; last CTA per M-tile writes out.
// ============================================================================
#define ROWB_  144
#define OFFB_  (128 * ROWB_)
#define STAGE_ ((128 + NT_) * ROWB_)     // 29952
#define NKB_   7

template<bool FUSE>
__global__ void __launch_bounds__(128)
gemm_fp16(const __half* __restrict__ A,
          const __half* __restrict__ Bh,
          const float* __restrict__ bias,    // [H_]
          const float* __restrict__ Wout,    // [1+H_] (FUSE)
          const float* __restrict__ bout,    // [1]    (FUSE)
          float* __restrict__ out,           // [B_]   (FUSE)
          __half* __restrict__ C) {          // (!FUSE)
    constexpr int CPR = 8;
    constexpr int NCH = (128 + NT_) * CPR;   // 1664
    constexpr int NIT = NCH / 128;           // 13

    extern __shared__ char smem_raw[];
    __shared__ float part[2][128];
    __shared__ int   s_done;
    const uint32_t sbase = smem_u32(smem_raw);

    const int tid  = threadIdx.x;
    const int warp = tid >> 5, lane = tid & 31;
    const int gr = lane >> 2, gc = lane & 3;
    const int wm  = (warp >> 1) * 64;    // warp row band (0 / 64)
    const int wni = warp & 1;
    const int wn  = wni * 40;            // warp col band (0 / 40)
    const int m0 = blockIdx.y * 128;
    const int n0 = blockIdx.x * NT_;

    const int lane8 = lane & 7;
    const int laneH = (lane >> 3) & 1;
    const int laneK = lane >> 4;
    const uint32_t aoff  = (uint32_t)((wm + lane8 + laneH * 8) * ROWB_ + laneK * 16);
    const uint32_t boff4 = (uint32_t)((wn + lane8 + laneK * 8) * ROWB_ + laneH * 16);
    const uint32_t boff2 = (uint32_t)((wn + 32 + lane8) * ROWB_ + laneH * 16);

    float acc[4][5][4];
    #pragma unroll
    for (int i = 0; i < 4; i++)
        #pragma unroll
        for (int j = 0; j < 5; j++)
            #pragma unroll
            for (int k = 0; k < 4; k++) acc[i][j][k] = 0.f;

    // ---- tile loader: 13 chunks/thread (A rows 0..127, B rows 128..207) ----
    #define LOAD_KB(KB, BUF)                                                        \
    do {                                                                            \
        const int k0_ = (KB) * 64;                                                  \
        const uint32_t st_ = sbase + (BUF) * STAGE_;                                \
        _Pragma("unroll")                                                           \
        for (int h = 0; h < NIT; h++) {                                             \
            int c_ = tid + h * 128;                                                 \
            int row_ = c_ / CPR, q_ = c_ % CPR;                                     \
            if (row_ < 128) {                                                       \
                CP16(st_ + row_ * ROWB_ + q_ * 16,                                  \
                     A + (size_t)(m0 + row_) * KP_ + k0_ + q_ * 8);                 \
            } else {                                                                \
                int r2_ = row_ - 128;                                               \
                CP16(st_ + OFFB_ + r2_ * ROWB_ + q_ * 16,                           \
                     Bh + (size_t)(n0 + r2_) * KP_ + k0_ + q_ * 8);                 \
            }                                                                       \
        }                                                                           \
    } while (0)

    LOAD_KB(0, 0);
    CP_COMMIT();

    for (int kb = 0; kb < NKB_; kb++) {
        const int buf = kb & 1;
        if (kb + 1 < NKB_) { LOAD_KB(kb + 1, buf ^ 1); CP_COMMIT(); CP_WAIT1(); }
        else               { CP_WAIT0(); }
        __syncthreads();

        const uint32_t st = sbase + buf * STAGE_;
        #pragma unroll
        for (int ks = 0; ks < 4; ks++) {
            const uint32_t ko = ks * 32;   // 16 fp16 = 32B
            uint32_t ah[4][4], bh[5][2];
            #pragma unroll
            for (int mi = 0; mi < 4; mi++) {
                uint32_t ad = st + aoff + mi * (16 * ROWB_) + ko;
                LDSM_X4(ah[mi][0], ah[mi][1], ah[mi][2], ah[mi][3], ad);
            }
            #pragma unroll
            for (int nj = 0; nj < 2; nj++) {
                uint32_t bd = st + OFFB_ + boff4 + nj * (16 * ROWB_) + ko;
                LDSM_X4(bh[nj*2][0], bh[nj*2][1], bh[nj*2+1][0], bh[nj*2+1][1], bd);
            }
            LDSM_X2(bh[4][0], bh[4][1], st + OFFB_ + boff2 + ko);

            #pragma unroll
            for (int mi = 0; mi < 4; mi++)
                #pragma unroll
                for (int ni = 0; ni < 5; ni++)
                    mma_fp16(acc[mi][ni], ah[mi][0], ah[mi][1], ah[mi][2], ah[mi][3],
                             bh[ni][0], bh[ni][1]);
        }
        __syncthreads();
    }
    #undef LOAD_KB

    // ---- epilogue (n always < 400: no N checks) ----
    if (!FUSE) {
        #pragma unroll
        for (int mi = 0; mi < 4; mi++) {
            int r = m0 + wm + mi * 16 + gr;
            #pragma unroll
            for (int ni = 0; ni < 5; ni++) {
                int n = n0 + wn + ni * 8 + gc * 2;
                float b0v = bias[n], b1v = bias[n + 1];
                #pragma unroll
                for (int half = 0; half < 2; half++) {
                    float x0 = fmaxf(acc[mi][ni][half * 2 + 0] + b0v, 0.f);
                    float x1 = fmaxf(acc[mi][ni][half * 2 + 1] + b1v, 0.f);
                    __half h0 = __float2half_rn(x0);
                    __half h1 = __float2half_rn(x1);
                    uint32_t ph = (uint32_t)__half_as_ushort(h0) |
                                  ((uint32_t)__half_as_ushort(h1) << 16);
                    size_t o = (size_t)(r + half * 8) * KP_ + n;
                    *reinterpret_cast<uint32_t*>(C + o) = ph;
                }
            }
        }
    } else {
        #pragma unroll
        for (int mi = 0; mi < 4; mi++) {
            float s0 = 0.f, s1 = 0.f;
            #pragma unroll
            for (int ni = 0; ni < 5; ni++) {
                int n = n0 + wn + ni * 8 + gc * 2;
                float w0v = Wout[1 + n], w1v = Wout[2 + n];
                float b0v = bias[n],     b1v = bias[n + 1];
                s0 = fmaf(fmaxf(acc[mi][ni][0] + b0v, 0.f), w0v, s0);
                s0 = fmaf(fmaxf(acc[mi][ni][1] + b1v, 0.f), w1v, s0);
                s1 = fmaf(fmaxf(acc[mi][ni][2] + b0v, 0.f), w0v, s1);
                s1 = fmaf(fmaxf(acc[mi][ni][3] + b1v, 0.f), w1v, s1);
            }
            s0 += __shfl_xor_sync(0xffffffffu, s0, 1);
            s0 += __shfl_xor_sync(0xffffffffu, s0, 2);
            s1 += __shfl_xor_sync(0xffffffffu, s1, 1);
            s1 += __shfl_xor_sync(0xffffffffu, s1, 2);
            if (gc == 0) {
                part[wni][wm + mi * 16 + gr]     = s0;
                part[wni][wm + mi * 16 + gr + 8] = s1;
            }
        }
        __syncthreads();
        g_part[blockIdx.x][m0 + tid] = part[0][tid] + part[1][tid];
        __threadfence();
        __syncthreads();
        if (tid == 0) s_done = atomicAdd(&g_cnt[blockIdx.y], 1);
        __syncthreads();
        if (s_done == 4) {            // last CTA of this M-tile: finish
            __threadfence();
            int b = m0 + tid;
            float s = g_part[0][b] + g_part[1][b] + g_part[2][b] +
                      g_part[3][b] + g_part[4][b];
            out[b] = fmaf(g_fm[b], Wout[0], bout[0] + s);
            if (tid == 0) g_cnt[blockIdx.y] = 0;   // reset for next replay
        }
    }
}

// ============================================================================
// Launch
// ============================================================================
static void* sym_addr(const void* symbol) {
    void* p = nullptr;
    cudaGetSymbolAddress(&p, symbol);
    return p;
}

extern "C" void kernel_launch(void* const* d_in, const int* in_sizes, int n_in,
                              void* d_out, int out_size) {
    const float* cont    = (const float*)d_in[0];
    const int*   cat     = (const int*)  d_in[1];
    const float* w_cont  = (const float*)d_in[2];
    const float* b_cont  = (const float*)d_in[3];
    const float* t_first = (const float*)d_in[4];
    const float* t_emb   = (const float*)d_in[5];
    const float* W1      = (const float*)d_in[6];
    const float* b1      = (const float*)d_in[7];
    const float* W2      = (const float*)d_in[8];
    const float* b2      = (const float*)d_in[9];
    const float* Wout    = (const float*)d_in[10];
    const float* bout    = (const float*)d_in[11];
    float* out = (float*)d_out;

    const int SMEM = 2 * STAGE_;   // 59904
    cudaFuncSetAttribute(gemm_fp16<false>, cudaFuncAttributeMaxDynamicSharedMemorySize, SMEM);
    cudaFuncSetAttribute(gemm_fp16<true>,  cudaFuncAttributeMaxDynamicSharedMemorySize, SMEM);

    __half* dnn = (__half*)sym_addr(g_dnn);
    __half* h1  = (__half*)sym_addr(g_h1);
    __half* w1t = (__half*)sym_addr(g_w1t);
    __half* w2t = (__half*)sym_addr(g_w2t);

    // 1) gather + FM + weight prep (single launch)
    gather_prep_kernel<<<GATHER_BLKS + PREP_BLKS, 256>>>(
        cont, cat, w_cont, b_cont, t_first, t_emb, W1, W2);

    // 2) h1 = relu(dnn_in @ W1 + b1)     grid: 5 N-tiles x 128 M-tiles
    dim3 grid(5, B_ / 128);
    gemm_fp16<false><<<grid, 128, SMEM>>>(dnn, w1t, b1, nullptr, nullptr, nullptr, h1);

    // 3) fused: h2 = relu(h1 @ W2 + b2); dot w/ Wout; last CTA writes out
    gemm_fp16<true><<<grid, 128, SMEM>>>(h1, w2t, b2, Wout, bout, out, nullptr);
}

// round 15
// speedup vs baseline: 1.7794x; 1.1373x over previous
#include <cuda_runtime.h>
#include <cuda_bf16.h>
#include <cuda_fp16.h>
#include <cstdint>

// ---------------- Problem constants ----------------
#define B_     16384
#define F_     26
#define V_     100000
#define E_     16
#define CONT_  13
#define K1_    429     // CONT_ + F_*E_
#define KP_    448     // padded K for BOTH GEMMs (mult of 64)
#define H_     400
#define NT_    80      // CTA N tile (5 * 80 = 400, exact)

// dnn_in layout (KP_): [ emb 0..415 | cont 416..428 | zero 429..447 ]
// h1 layout (KP_):     [ h1 0..399 | zero 400..447 ]  (pad never written; zero-init)

// ---------------- Scratch (device globals) ----------------
__device__ __align__(256) __half g_dnn [(size_t)B_ * KP_];
__device__ __align__(256) __half g_h1  [(size_t)B_ * KP_];
__device__ __align__(256) __half g_w1t [(size_t)H_ * KP_];
__device__ __align__(256) __half g_w2t [(size_t)H_ * KP_];
__device__ float g_fm  [B_];
__device__ float g_part[5][B_];
__device__ int   g_cnt1[B_ / 128];      // GEMM1->GEMM2 tile readiness (self-reset)
__device__ int   g_cnt [B_ / 128];      // GEMM2 finish counter (self-reset)

// ---------------- PTX helpers ----------------
__device__ __forceinline__ uint32_t smem_u32(const void* p) {
    return (uint32_t)__cvta_generic_to_shared(p);
}
__device__ __forceinline__ int ld_acquire(const int* p) {
    int v;
    asm volatile("ld.acquire.gpu.global.s32 %0, [%1];" : "=r"(v) : "l"(p));
    return v;
}
#define CP16(dst_u32, src) \
    asm volatile("cp.async.cg.shared.global [%0], [%1], 16;" :: "r"(dst_u32), "l"(src))
#define CP_COMMIT() asm volatile("cp.async.commit_group;" ::: "memory")
#define CP_WAIT0()  asm volatile("cp.async.wait_group 0;" ::: "memory")
#define CP_WAIT1()  asm volatile("cp.async.wait_group 1;" ::: "memory")

#define LDSM_X4(r0, r1, r2, r3, addr)                                          \
    asm volatile("ldmatrix.sync.aligned.m8n8.x4.shared.b16 {%0,%1,%2,%3},[%4];"\
                 : "=r"(r0), "=r"(r1), "=r"(r2), "=r"(r3) : "r"(addr))
#define LDSM_X2(r0, r1, addr)                                                  \
    asm volatile("ldmatrix.sync.aligned.m8n8.x2.shared.b16 {%0,%1},[%2];"      \
                 : "=r"(r0), "=r"(r1) : "r"(addr))

__device__ __forceinline__ void mma_fp16(float* c,
                                         uint32_t a0, uint32_t a1, uint32_t a2, uint32_t a3,
                                         uint32_t b0, uint32_t b1) {
    asm volatile(
        "mma.sync.aligned.m16n8k16.row.col.f32.f16.f16.f32 "
        "{%0,%1,%2,%3},{%4,%5,%6,%7},{%8,%9},{%0,%1,%2,%3};"
        : "+f"(c[0]), "+f"(c[1]), "+f"(c[2]), "+f"(c[3])
        : "r"(a0), "r"(a1), "r"(a2), "r"(a3), "r"(b0), "r"(b1));
}

// ============================================================================
// Kernel 1 (merged): blocks [0, 2048): gather + FM (one warp per sample);
//                    blocks [2048, 2748): weight prep.
//   FM reduction via smem transpose (lanes 0..15 sum one component over the
//   26 fields) -> ~10 shuffles per sample instead of ~90.
// ============================================================================
#define GATHER_BLKS (B_ / 8)     // 2048
#define PREP_BLKS   700          // ceil(400*448 / 256)

__global__ void gather_prep_kernel(const float* __restrict__ cont,
                                   const int*   __restrict__ cat,
                                   const float* __restrict__ w_cont,
                                   const float* __restrict__ b_cont,
                                   const float* __restrict__ t_first,
                                   const float* __restrict__ t_emb,
                                   const float* __restrict__ W1,
                                   const float* __restrict__ W2) {
    if (blockIdx.x >= GATHER_BLKS) {
        int idx = (blockIdx.x - GATHER_BLKS) * 256 + threadIdx.x;
        if (idx < H_ * KP_) {
            int n = idx / KP_, k = idx % KP_;
            float v1;
            if (k < 416)      v1 = W1[(size_t)(CONT_ + k) * H_ + n];   // emb part
            else if (k < 429) v1 = W1[(size_t)(k - 416) * H_ + n];     // cont part
            else              v1 = 0.f;
            g_w1t[idx] = __float2half_rn(v1);

            float v2 = (k < H_) ? W2[(size_t)k * H_ + n] : 0.f;
            g_w2t[idx] = __float2half_rn(v2);
        }
        return;
    }

    __shared__ float sm[8][F_][17];
    int wid  = threadIdx.x >> 5;
    int lane = threadIdx.x & 31;
    const int b = blockIdx.x * 8 + wid;

    float scal = 0.f;

    if (lane < F_) {
        int idx = cat[b * F_ + lane];
        const float4* row =
            reinterpret_cast<const float4*>(t_emb + ((size_t)lane * V_ + (size_t)idx) * E_);
        float4 r0 = row[0], r1 = row[1], r2 = row[2], r3 = row[3];
        float v[16] = {r0.x,r0.y,r0.z,r0.w, r1.x,r1.y,r1.z,r1.w,
                       r2.x,r2.y,r2.z,r2.w, r3.x,r3.y,r3.z,r3.w};

        uint32_t pk[8];
        #pragma unroll
        for (int i = 0; i < 8; i++) {
            __half h0 = __float2half_rn(v[2*i]);
            __half h1 = __float2half_rn(v[2*i+1]);
            pk[i] = (uint32_t)__half_as_ushort(h0) | ((uint32_t)__half_as_ushort(h1) << 16);
        }
        uint4* dst = reinterpret_cast<uint4*>(g_dnn + (size_t)b * KP_ + lane * E_);
        dst[0] = make_uint4(pk[0], pk[1], pk[2], pk[3]);
        dst[1] = make_uint4(pk[4], pk[5], pk[6], pk[7]);

        #pragma unroll
        for (int e = 0; e < 16; e++) sm[wid][lane][e] = v[e];

        scal = t_first[(size_t)lane * V_ + (size_t)idx];
    }
    if (lane < CONT_) {
        float c = cont[b * CONT_ + lane];
        g_dnn[(size_t)b * KP_ + 416 + lane] = __float2half_rn(c);
        scal = fmaf(c, w_cont[lane], scal);
    }
    if (lane < KP_ - K1_) {     // zero cols 429..447 (19 lanes)
        g_dnn[(size_t)b * KP_ + K1_ + lane] = __ushort_as_half((unsigned short)0);
    }
    __syncwarp();

    // lanes 0..15: pe = S_e^2 - sum_f v_fe^2
    float pe = 0.f;
    if (lane < 16) {
        float S = 0.f, qe = 0.f;
        #pragma unroll
        for (int f = 0; f < F_; f++) {
            float x = sm[wid][f][lane];
            S += x;
            qe = fmaf(x, x, qe);
        }
        pe = fmaf(S, S, -qe);
    }
    #pragma unroll
    for (int off = 16; off; off >>= 1) {
        pe   += __shfl_xor_sync(0xffffffffu, pe,   off);
        scal += __shfl_xor_sync(0xffffffffu, scal, off);
    }
    if (lane == 0) {
        g_fm[b] = scal + b_cont[0] + 0.5f * pe;
    }
}

// ============================================================================
// Merged GEMM kernel: 1280 CTAs.
//   bid < 640 : GEMM1 tile (y = bid/5, x = bid%5): h1 = relu(dnn@W1+b1);
//               after stores: fence + increment g_cnt1[y].
//   bid >= 640: GEMM2 tile: spin until g_cnt1[y]==5; compute dot with Wout;
//               last CTA per tile writes out and resets both counters.
//   CTA 128(M) x 80(N), 4 warps, warp tile 64x40, BK=64, K=448 (7 k-blocks).
// ============================================================================
#define ROWB_  144
#define OFFB_  (128 * ROWB_)
#define STAGE_ ((128 + NT_) * ROWB_)     // 29952
#define NKB_   7
#define G1BLKS (5 * (B_ / 128))          // 640

__global__ void __launch_bounds__(128)
gemm_merged(const __half* __restrict__ dnn, const __half* __restrict__ h1g,
            const __half* __restrict__ w1t, const __half* __restrict__ w2t,
            const float* __restrict__ b1,   const float* __restrict__ b2,
            const float* __restrict__ Wout, const float* __restrict__ bout,
            float* __restrict__ out) {
    constexpr int CPR = 8;
    constexpr int NCH = (128 + NT_) * CPR;   // 1664
    constexpr int NIT = NCH / 128;           // 13

    extern __shared__ char smem_raw[];
    __shared__ float part[2][128];
    __shared__ int   s_done;
    const uint32_t sbase = smem_u32(smem_raw);

    const int bid    = blockIdx.x;
    const bool p2    = (bid >= G1BLKS);
    const int lbid   = p2 ? bid - G1BLKS : bid;
    const int by     = lbid / 5;
    const int bx     = lbid % 5;

    const __half* A    = p2 ? h1g : dnn;
    const __half* Bw   = p2 ? w2t : w1t;
    const float*  bias = p2 ? b2  : b1;

    const int tid  = threadIdx.x;
    const int warp = tid >> 5, lane = tid & 31;
    const int gr = lane >> 2, gc = lane & 3;
    const int wm  = (warp >> 1) * 64;
    const int wni = warp & 1;
    const int wn  = wni * 40;
    const int m0 = by * 128;
    const int n0 = bx * NT_;

    const int lane8 = lane & 7;
    const int laneH = (lane >> 3) & 1;
    const int laneK = lane >> 4;
    const uint32_t aoff  = (uint32_t)((wm + lane8 + laneH * 8) * ROWB_ + laneK * 16);
    const uint32_t boff4 = (uint32_t)((wn + lane8 + laneK * 8) * ROWB_ + laneH * 16);
    const uint32_t boff2 = (uint32_t)((wn + 32 + lane8) * ROWB_ + laneH * 16);

    // GEMM2: wait until all 5 GEMM1 CTAs of this M-tile have committed h1
    if (p2) {
        if (tid == 0) {
            while (ld_acquire(&g_cnt1[by]) != 5) __nanosleep(64);
        }
        __syncthreads();
    }

    float acc[4][5][4];
    #pragma unroll
    for (int i = 0; i < 4; i++)
        #pragma unroll
        for (int j = 0; j < 5; j++)
            #pragma unroll
            for (int k = 0; k < 4; k++) acc[i][j][k] = 0.f;

    #define LOAD_KB(KB, BUF)                                                        \
    do {                                                                            \
        const int k0_ = (KB) * 64;                                                  \
        const uint32_t st_ = sbase + (BUF) * STAGE_;                                \
        _Pragma("unroll")                                                           \
        for (int h = 0; h < NIT; h++) {                                             \
            int c_ = tid + h * 128;                                                 \
            int row_ = c_ / CPR, q_ = c_ % CPR;                                     \
            if (row_ < 128) {                                                       \
                CP16(st_ + row_ * ROWB_ + q_ * 16,                                  \
                     A + (size_t)(m0 + row_) * KP_ + k0_ + q_ * 8);                 \
            } else {                                                                \
                int r2_ = row_ - 128;                                               \
                CP16(st_ + OFFB_ + r2_ * ROWB_ + q_ * 16,                           \
                     Bw + (size_t)(n0 + r2_) * KP_ + k0_ + q_ * 8);                 \
            }                                                                       \
        }                                                                           \
    } while (0)

    LOAD_KB(0, 0);
    CP_COMMIT();

    for (int kb = 0; kb < NKB_; kb++) {
        const int buf = kb & 1;
        if (kb + 1 < NKB_) { LOAD_KB(kb + 1, buf ^ 1); CP_COMMIT(); CP_WAIT1(); }
        else               { CP_WAIT0(); }
        __syncthreads();

        const uint32_t st = sbase + buf * STAGE_;
        #pragma unroll
        for (int ks = 0; ks < 4; ks++) {
            const uint32_t ko = ks * 32;
            uint32_t ah[4][4], bh[5][2];
            #pragma unroll
            for (int mi = 0; mi < 4; mi++) {
                uint32_t ad = st + aoff + mi * (16 * ROWB_) + ko;
                LDSM_X4(ah[mi][0], ah[mi][1], ah[mi][2], ah[mi][3], ad);
            }
            #pragma unroll
            for (int nj = 0; nj < 2; nj++) {
                uint32_t bd = st + OFFB_ + boff4 + nj * (16 * ROWB_) + ko;
                LDSM_X4(bh[nj*2][0], bh[nj*2][1], bh[nj*2+1][0], bh[nj*2+1][1], bd);
            }
            LDSM_X2(bh[4][0], bh[4][1], st + OFFB_ + boff2 + ko);

            #pragma unroll
            for (int mi = 0; mi < 4; mi++)
                #pragma unroll
                for (int ni = 0; ni < 5; ni++)
                    mma_fp16(acc[mi][ni], ah[mi][0], ah[mi][1], ah[mi][2], ah[mi][3],
                             bh[ni][0], bh[ni][1]);
        }
        __syncthreads();
    }
    #undef LOAD_KB

    if (!p2) {
        // ---- GEMM1 epilogue: relu(+bias) -> h1 fp16 (ldc=KP_) ----
        #pragma unroll
        for (int mi = 0; mi < 4; mi++) {
            int r = m0 + wm + mi * 16 + gr;
            #pragma unroll
            for (int ni = 0; ni < 5; ni++) {
                int n = n0 + wn + ni * 8 + gc * 2;
                float b0v = bias[n], b1v = bias[n + 1];
                #pragma unroll
                for (int half = 0; half < 2; half++) {
                    float x0 = fmaxf(acc[mi][ni][half * 2 + 0] + b0v, 0.f);
                    float x1 = fmaxf(acc[mi][ni][half * 2 + 1] + b1v, 0.f);
                    __half h0 = __float2half_rn(x0);
                    __half h1 = __float2half_rn(x1);
                    uint32_t ph = (uint32_t)__half_as_ushort(h0) |
                                  ((uint32_t)__half_as_ushort(h1) << 16);
                    size_t o = (size_t)(r + half * 8) * KP_ + n;
                    *reinterpret_cast<uint32_t*>(const_cast<__half*>(h1g) + o) = ph;
                }
            }
        }
        __threadfence();
        __syncthreads();
        if (tid == 0) atomicAdd(&g_cnt1[by], 1);
    } else {
        // ---- GEMM2 epilogue: dot with Wout; last CTA per tile writes out ----
        #pragma unroll
        for (int mi = 0; mi < 4; mi++) {
            float s0 = 0.f, s1 = 0.f;
            #pragma unroll
            for (int ni = 0; ni < 5; ni++) {
                int n = n0 + wn + ni * 8 + gc * 2;
                float w0v = Wout[1 + n], w1v = Wout[2 + n];
                float b0v = bias[n],     b1v = bias[n + 1];
                s0 = fmaf(fmaxf(acc[mi][ni][0] + b0v, 0.f), w0v, s0);
                s0 = fmaf(fmaxf(acc[mi][ni][1] + b1v, 0.f), w1v, s0);
                s1 = fmaf(fmaxf(acc[mi][ni][2] + b0v, 0.f), w0v, s1);
                s1 = fmaf(fmaxf(acc[mi][ni][3] + b1v, 0.f), w1v, s1);
            }
            s0 += __shfl_xor_sync(0xffffffffu, s0, 1);
            s0 += __shfl_xor_sync(0xffffffffu, s0, 2);
            s1 += __shfl_xor_sync(0xffffffffu, s1, 1);
            s1 += __shfl_xor_sync(0xffffffffu, s1, 2);
            if (gc == 0) {
                part[wni][wm + mi * 16 + gr]     = s0;
                part[wni][wm + mi * 16 + gr + 8] = s1;
            }
        }
        __syncthreads();
        g_part[bx][m0 + tid] = part[0][tid] + part[1][tid];
        __threadfence();
        __syncthreads();
        if (tid == 0) s_done = atomicAdd(&g_cnt[by], 1);
        __syncthreads();
        if (s_done == 4) {            // last GEMM2 CTA of this M-tile
            __threadfence();
            int b = m0 + tid;
            float s = g_part[0][b] + g_part[1][b] + g_part[2][b] +
                      g_part[3][b] + g_part[4][b];
            out[b] = fmaf(g_fm[b], Wout[0], bout[0] + s);
            if (tid == 0) {           // reset counters for next graph replay
                g_cnt[by]  = 0;
                g_cnt1[by] = 0;
            }
        }
    }
}

// ============================================================================
// Launch
// ============================================================================
static void* sym_addr(const void* symbol) {
    void* p = nullptr;
    cudaGetSymbolAddress(&p, symbol);
    return p;
}

extern "C" void kernel_launch(void* const* d_in, const int* in_sizes, int n_in,
                              void* d_out, int out_size) {
    const float* cont    = (const float*)d_in[0];
    const int*   cat     = (const int*)  d_in[1];
    const float* w_cont  = (const float*)d_in[2];
    const float* b_cont  = (const float*)d_in[3];
    const float* t_first = (const float*)d_in[4];
    const float* t_emb   = (const float*)d_in[5];
    const float* W1      = (const float*)d_in[6];
    const float* b1      = (const float*)d_in[7];
    const float* W2      = (const float*)d_in[8];
    const float* b2      = (const float*)d_in[9];
    const float* Wout    = (const float*)d_in[10];
    const float* bout    = (const float*)d_in[11];
    float* out = (float*)d_out;

    const int SMEM = 2 * STAGE_;   // 59904
    cudaFuncSetAttribute(gemm_merged, cudaFuncAttributeMaxDynamicSharedMemorySize, SMEM);

    __half* dnn = (__half*)sym_addr(g_dnn);
    __half* h1  = (__half*)sym_addr(g_h1);
    __half* w1t = (__half*)sym_addr(g_w1t);
    __half* w2t = (__half*)sym_addr(g_w2t);

    // 1) gather + FM + weight prep (single launch)
    gather_prep_kernel<<<GATHER_BLKS + PREP_BLKS, 256>>>(
        cont, cat, w_cont, b_cont, t_first, t_emb, W1, W2);

    // 2) merged GEMM1 + GEMM2 (+finish): 640 + 640 CTAs, software pipelined
    gemm_merged<<<2 * G1BLKS, 128, SMEM>>>(dnn, h1, w1t, w2t,
                                           b1, b2, Wout, bout, out);
}